// round 3
// baseline (speedup 1.0000x reference)
#include <cuda_runtime.h>

// MPS forward: y_{n+1}[b] = act( sum_{a,i} y_n[a] * A[c,site,a,i,b] * x[batch,i,site] )
// BATCH=1024, CHANNEL=10, LENGTH=784, CHI=64, D=2.
// One block = 1 channel x 16 batches; thread (bl,g) = batch bl, columns
// {4g..4g+3} U {32+4g..35+4g} (layout chosen so every A LDS.128 is
// conflict-free: 8 distinct 16B addresses within one 128B line, 4-way
// broadcast across batch lanes).

namespace {
constexpr int LEN = 784;
constexpr int NCH = 10;
constexpr int TB  = 16;    // batches per block
constexpr int NT  = 128;   // threads per block (TB * 8 groups)
constexpr int YP  = 72;    // y row pitch in floats (bank-friendly, 16B-aligned)
}

__device__ __forceinline__ float act_sig(float v) {
    // (tanh(v)+1)/2 == sigmoid(2v)
    return __fdividef(1.0f, 1.0f + __expf(-2.0f * v));
}

__global__ void __launch_bounds__(NT)
mps_kernel(const float* __restrict__ x,
           const float* __restrict__ tens,
           float* __restrict__ out)
{
    __shared__ __align__(16) float As[8192];          // one site: [a=64][i=2][b=64]
    __shared__ __align__(16) float Ys[2][TB * YP];    // ping-pong carried state

    const int tid   = threadIdx.x;
    const int g     = tid & 7;        // column group 0..7
    const int bl    = tid >> 3;       // local batch 0..15
    const int c     = blockIdx.x % NCH;
    const int tile  = blockIdx.x / NCH;
    const int batch = tile * TB + bl;

    const float* __restrict__ xb = x    + (size_t)batch * (2 * LEN);
    const float* __restrict__ Tc = tens + (size_t)c * LEN * 8192;

    // init y (input of site 0): y[a] = (a == 0) ? 1 : 0
    {
        float4 zlo = make_float4(g == 0 ? 1.0f : 0.0f, 0.f, 0.f, 0.f);
        float4 zhi = make_float4(0.f, 0.f, 0.f, 0.f);
        *reinterpret_cast<float4*>(&Ys[0][bl * YP + 4 * g])      = zlo;
        *reinterpret_cast<float4*>(&Ys[0][bl * YP + 32 + 4 * g]) = zhi;
    }

    // load A for site 0 (linear copy; 128 threads x 16 float4 = 8192 floats)
    {
        const float4* src = reinterpret_cast<const float4*>(Tc);
        float4*       dst = reinterpret_cast<float4*>(As);
        #pragma unroll
        for (int k = 0; k < 16; ++k)
            dst[k * NT + tid] = src[k * NT + tid];
    }
    __syncthreads();

    int p = 0;
    for (int site = 0; site < LEN; ++site) {
        // prefetch next site's A into registers (overlaps gmem latency with FMA loop)
        float4 pf[16];
        const bool has_next = (site + 1 < LEN);
        if (has_next) {
            const float4* nsrc =
                reinterpret_cast<const float4*>(Tc + (size_t)(site + 1) * 8192);
            #pragma unroll
            for (int k = 0; k < 16; ++k)
                pf[k] = nsrc[k * NT + tid];
        }

        const float x0 = xb[site];
        const float x1 = xb[LEN + site];

        float4 z0a = {}, z0b = {}, z1a = {}, z1b = {};
        const float* yr = &Ys[p][bl * YP];

        #pragma unroll 4
        for (int a4 = 0; a4 < 16; ++a4) {
            const float4 y4 = *reinterpret_cast<const float4*>(yr + 4 * a4);
            #pragma unroll
            for (int j = 0; j < 4; ++j) {
                const float ya = (j == 0) ? y4.x : (j == 1) ? y4.y
                               : (j == 2) ? y4.z : y4.w;
                const float4* Ar =
                    reinterpret_cast<const float4*>(As + (4 * a4 + j) * 128);
                const float4 q0 = Ar[g];        // i=0, cols 4g..4g+3
                const float4 q1 = Ar[8 + g];    // i=0, cols 32+4g..
                const float4 q2 = Ar[16 + g];   // i=1, cols 4g..
                const float4 q3 = Ar[24 + g];   // i=1, cols 32+4g..
                z0a.x = fmaf(ya, q0.x, z0a.x); z0a.y = fmaf(ya, q0.y, z0a.y);
                z0a.z = fmaf(ya, q0.z, z0a.z); z0a.w = fmaf(ya, q0.w, z0a.w);
                z0b.x = fmaf(ya, q1.x, z0b.x); z0b.y = fmaf(ya, q1.y, z0b.y);
                z0b.z = fmaf(ya, q1.z, z0b.z); z0b.w = fmaf(ya, q1.w, z0b.w);
                z1a.x = fmaf(ya, q2.x, z1a.x); z1a.y = fmaf(ya, q2.y, z1a.y);
                z1a.z = fmaf(ya, q2.z, z1a.z); z1a.w = fmaf(ya, q2.w, z1a.w);
                z1b.x = fmaf(ya, q3.x, z1b.x); z1b.y = fmaf(ya, q3.y, z1b.y);
                z1b.z = fmaf(ya, q3.z, z1b.z); z1b.w = fmaf(ya, q3.w, z1b.w);
            }
        }

        if (!has_next) {
            // last site: no activation; dims[784]==1 -> only column 0 matters
            if (g == 0)
                out[(size_t)batch * NCH + c] = fmaf(x0, z0a.x, x1 * z1a.x);
        } else {
            // bond dimension for the output of this site
            const int nn = site + 1;
            const int up = (nn >= 6) ? 64 : (1 << nn);
            const int dn = ((LEN - nn) >= 6) ? 64 : (1 << (LEN - nn));
            const int dnext = (up < dn) ? up : dn;

            float4 va, vb;
            va.x = fmaf(x0, z0a.x, x1 * z1a.x);
            va.y = fmaf(x0, z0a.y, x1 * z1a.y);
            va.z = fmaf(x0, z0a.z, x1 * z1a.z);
            va.w = fmaf(x0, z0a.w, x1 * z1a.w);
            vb.x = fmaf(x0, z0b.x, x1 * z1b.x);
            vb.y = fmaf(x0, z0b.y, x1 * z1b.y);
            vb.z = fmaf(x0, z0b.z, x1 * z1b.z);
            vb.w = fmaf(x0, z0b.w, x1 * z1b.w);

            const int clo = 4 * g;
            const int chi = 32 + 4 * g;
            float4 oa, ob;
            oa.x = (clo + 0 < dnext) ? act_sig(va.x) : 0.f;
            oa.y = (clo + 1 < dnext) ? act_sig(va.y) : 0.f;
            oa.z = (clo + 2 < dnext) ? act_sig(va.z) : 0.f;
            oa.w = (clo + 3 < dnext) ? act_sig(va.w) : 0.f;
            ob.x = (chi + 0 < dnext) ? act_sig(vb.x) : 0.f;
            ob.y = (chi + 1 < dnext) ? act_sig(vb.y) : 0.f;
            ob.z = (chi + 2 < dnext) ? act_sig(vb.z) : 0.f;
            ob.w = (chi + 3 < dnext) ? act_sig(vb.w) : 0.f;

            float* yw = &Ys[1 - p][bl * YP];
            *reinterpret_cast<float4*>(yw + clo) = oa;
            *reinterpret_cast<float4*>(yw + chi) = ob;

            __syncthreads();   // everyone done reading As (and y writes visible)
            {
                float4* dst = reinterpret_cast<float4*>(As);
                #pragma unroll
                for (int k = 0; k < 16; ++k)
                    dst[k * NT + tid] = pf[k];
            }
            __syncthreads();   // new A visible
            p ^= 1;
        }
    }
}

extern "C" void kernel_launch(void* const* d_in, const int* in_sizes, int n_in,
                              void* d_out, int out_size)
{
    const float* a0 = (const float*)d_in[0];
    const float* a1 = (const float*)d_in[1];
    // x has 1024*2*784 = 1,605,632 elems; tensors 10*784*64*2*64 = 64,225,280.
    const float* x = a0;
    const float* t = a1;
    if (n_in >= 2 && in_sizes[0] > in_sizes[1]) { x = a1; t = a0; }

    const int blocks = NCH * (1024 / TB);   // 10 * 64 = 640
    mps_kernel<<<blocks, NT>>>(x, t, (float*)d_out);
}